// round 12
// baseline (speedup 1.0000x reference)
#include <cuda_runtime.h>
#include <cuda_bf16.h>
#include <cstdint>

#define NB 512      // batch
#define NT 256      // time steps
#define NF 128      // features
#define NH 1024     // hidden
#define NZ 4096     // 4*H
#define KTOT 1152   // NF + NH
#define FEATP 2064  // padded feature length
#define FEATR 2050  // real feature length

// ------------------ device scratch (no allocation allowed) ------------------
// Fragment-layout arrays, hi/lo interleaved per 1KB block: [hi 512B][lo 512B].
__device__ __align__(16) __nv_bfloat16 g_Wf[(size_t)NZ * KTOT * 2];      // W^T frag blocks [J][72]
__device__ __align__(16) __nv_bfloat16 g_xf[(size_t)NB * NT * NF * 2];   // x frag blocks [mb][NT][8]
__device__ __align__(16) __nv_bfloat16 g_hf2[2 * (size_t)NB * NH * 2];   // h frag blocks [buf][mb][64]
__device__ float g_c[NB * NH];
__device__ float g_hf[NB * NH];
__device__ float g_feat[NB * FEATP];
__device__ float g_vlp[NB * 512];
__device__ float g_qlp[NB * 512];
__device__ float g_vle[NB * 512];
__device__ float g_qle[NB * 512];
__device__ float g_sq[NB];

// ------------------ helpers ------------------
#define MMA16816(d, a, b) \
    asm volatile("mma.sync.aligned.m16n8k16.row.col.f32.bf16.bf16.f32 " \
                 "{%0,%1,%2,%3}, {%4,%5,%6,%7}, {%8,%9}, {%0,%1,%2,%3};" \
                 : "+f"((d)[0]), "+f"((d)[1]), "+f"((d)[2]), "+f"((d)[3]) \
                 : "r"((a)[0]), "r"((a)[1]), "r"((a)[2]), "r"((a)[3]), \
                   "r"((b)[0]), "r"((b)[1]))

__device__ __forceinline__ float fsig(float x)
{
    float e = __expf(-x);
    return __fdividef(1.f, 1.f + e);
}
__device__ __forceinline__ float ftanh(float x)
{
    float e = __expf(2.f * x);
    return 1.f - __fdividef(2.f, e + 1.f);
}

// ------------------ prep kernels ------------------
__global__ void k_init()
{
    int i = blockIdx.x * blockDim.x + threadIdx.x;
    if (i < NB * NH) g_c[i] = 0.f;
    if (i < NB * NH * 2) g_hf2[i] = __float2bfloat16(0.f);   // h buffer 0
}

// W -> permuted (col j = u*4+gate), split hi/lo, B-fragment layout, hi/lo interleaved blocks.
__global__ void k_prep_w(const float* __restrict__ W)
{
    int id = blockIdx.x * blockDim.x + threadIdx.x;
    if (id >= NZ * KTOT) return;
    int j = id / KTOT;
    int k = id - j * KTOT;
    int u = j >> 2;
    int g = j & 3;
    float w = W[(size_t)k * NZ + g * NH + u];
    __nv_bfloat16 hi = __float2bfloat16(w);
    float lo = w - __bfloat162float(hi);
    int J = j >> 4;
    int n16 = j & 15;
    int K16 = k >> 4;
    int kk = k & 15;
    int lane = (n16 & 7) * 4 + ((kk & 7) >> 1);
    int reg = (n16 >> 3) * 2 + (kk >> 3);
    int half = kk & 1;
    size_t out = ((size_t)J * 72 + K16) * 512 + lane * 8 + reg * 2 + half;
    g_Wf[out] = hi;
    g_Wf[out + 256] = __float2bfloat16(lo);
}

// history -> split hi/lo, A-fragment layout, hi/lo interleaved blocks [mb][t][kb].
__global__ void k_prep_x(const float* __restrict__ hist)
{
    int id = blockIdx.x * blockDim.x + threadIdx.x;
    if (id >= NB * NT * NF) return;
    int b = id / (NT * NF);
    int r = id - b * (NT * NF);
    int t = r / NF;
    int f = r - t * NF;
    float v = hist[id];
    __nv_bfloat16 hi = __float2bfloat16(v);
    float lo = v - __bfloat162float(hi);
    int mb = b >> 4, row = b & 15;
    int kb = f >> 4, kk = f & 15;
    int lane = (row & 7) * 4 + ((kk & 7) >> 1);
    int reg = (row >> 3) + 2 * (kk >> 3);
    int half = kk & 1;
    size_t out = ((size_t)(mb * NT + t) * 8 + kb) * 512 + lane * 8 + reg * 2 + half;
    g_xf[out] = hi;
    g_xf[out + 256] = __float2bfloat16(lo);
}

// ------------------ fused LSTM step: smem-free fragment-direct GEMM + cell ------------------
// grid (128 n-tiles, 4 m-tiles) = 512 CTAs, 3 CTAs/SM. 256 threads (8 warps, 4m x 2n,
// warp tile 32m x 16n: acc 16 regs). No smem, no barriers.
// A prefetch depth 2, B depth 3. K loop unrolled by 6.
__global__ __launch_bounds__(256, 3) void k_step(const float* __restrict__ blstm, int t)
{
    const int tid = threadIdx.x;
    const int wid = tid >> 5;
    const int lane = tid & 31;
    const int ntile = blockIdx.x;      // 0..127 (32 cols each)
    const int mtile = blockIdx.y;      // 0..3
    const int wm = wid & 3;            // 4 warp rows of 32 m
    const int wn = wid >> 2;           // 2 warp cols of 16 n
    const int m0 = mtile * 128;

    const size_t HB = (size_t)NB * NH * 2;
    const size_t hrd = (size_t)(t & 1) * HB;
    const size_t hwr = (size_t)((t + 1) & 1) * HB;

    float acc[2][2][4];
#pragma unroll
    for (int a = 0; a < 2; ++a)
#pragma unroll
        for (int b = 0; b < 2; ++b)
#pragma unroll
            for (int cc = 0; cc < 4; ++cc) acc[a][b][cc] = 0.f;

    const int mbG0 = mtile * 8 + wm * 2;
    const int J = ntile * 2 + wn;          // single 16-col block per warp

    const __nv_bfloat16* pX = g_xf + ((size_t)(mbG0 * NT + t) * 8) * 512 + lane * 8;
    const __nv_bfloat16* pH = g_hf2 + hrd + ((size_t)mbG0 * 64) * 512 + lane * 8;
    const __nv_bfloat16* pB = g_Wf + ((size_t)J * 72) * 512 + lane * 8;

    const size_t XMT = (size_t)NT * 8 * 512;   // x mt stride (elems)
    const size_t HMT = (size_t)64 * 512;       // h mt stride

    uint4 Ah[2][2], Al[2][2];   // [buf][mt]
    uint4 Bh[3], Bl[3];         // [buf]

    auto ldA = [&](int s, int buf) {
        const __nv_bfloat16* base;
        size_t mts;
        if (s < 8) { base = pX + (size_t)s * 512; mts = XMT; }
        else       { base = pH + (size_t)(s - 8) * 512; mts = HMT; }
        Ah[buf][0] = *(const uint4*)(base);
        Al[buf][0] = *(const uint4*)(base + 256);
        Ah[buf][1] = *(const uint4*)(base + mts);
        Al[buf][1] = *(const uint4*)(base + mts + 256);
    };
    auto ldB = [&](int s, int buf) {
        const __nv_bfloat16* base = pB + (size_t)s * 512;
        Bh[buf] = *(const uint4*)(base);
        Bl[buf] = *(const uint4*)(base + 256);
    };

    auto domma = [&](int ia, int ib) {
        // term-major: hh, hl, lh (same per-accumulator order as rounds 9/10)
#pragma unroll
        for (int mt = 0; mt < 2; ++mt)
#pragma unroll
            for (int nt = 0; nt < 2; ++nt)
                MMA16816(acc[mt][nt], ((uint32_t*)&Ah[ia][mt]),
                         ((uint32_t*)&Bh[ib]) + nt * 2);
#pragma unroll
        for (int mt = 0; mt < 2; ++mt)
#pragma unroll
            for (int nt = 0; nt < 2; ++nt)
                MMA16816(acc[mt][nt], ((uint32_t*)&Ah[ia][mt]),
                         ((uint32_t*)&Bl[ib]) + nt * 2);
#pragma unroll
        for (int mt = 0; mt < 2; ++mt)
#pragma unroll
            for (int nt = 0; nt < 2; ++nt)
                MMA16816(acc[mt][nt], ((uint32_t*)&Al[ia][mt]),
                         ((uint32_t*)&Bh[ib]) + nt * 2);
    };

    ldA(0, 0);
    ldB(0, 0);
    ldA(1, 1);
    ldB(1, 1);
    ldB(2, 2);

#pragma unroll 1
    for (int s = 0; s < 72; s += 6) {
#pragma unroll
        for (int i = 0; i < 6; ++i) {
            const int q = s + i;
            domma(i & 1, i % 3);
            if (q + 2 < 72) ldA(q + 2, i & 1);
            if (q + 3 < 72) ldB(q + 3, i % 3);
        }
    }

    // ---- fused cell epilogue (register accumulators) ----
    const int g = lane >> 2;
    const int tq = lane & 3;
    const bool even = (tq & 1) == 0;
    const bool last = (t == NT - 1);
#pragma unroll
    for (int mt = 0; mt < 2; ++mt) {
#pragma unroll
        for (int nt = 0; nt < 2; ++nt) {
            float c0 = acc[mt][nt][0], c1 = acc[mt][nt][1];
            float c2 = acc[mt][nt][2], c3 = acc[mt][nt][3];
            float s0 = even ? c2 : c0;
            float s1 = even ? c3 : c1;
            float r0 = __shfl_xor_sync(0xffffffffu, s0, 1);
            float r1 = __shfl_xor_sync(0xffffffffu, s1, 1);
            float zi, zj, zf, zo;
            int row;
            if (even) { row = g;     zi = c0; zj = c1; zf = r0; zo = r1; }
            else      { row = g + 8; zi = r0; zj = r1; zf = c2; zo = c3; }
            int u = J * 4 + nt * 2 + (tq >> 1);
            int m = m0 + wm * 32 + mt * 16 + row;
            float bi = blstm[u];
            float bj = blstm[NH + u];
            float bf_ = blstm[2 * NH + u];
            float bo = blstm[3 * NH + u];
            size_t idx = (size_t)m * NH + u;
            float cold = g_c[idx];
            float cn = fsig(zf + bf_ + 1.f) * cold + fsig(zi + bi) * ftanh(zj + bj);
            float h = fsig(zo + bo) * ftanh(cn);
            g_c[idx] = cn;
            if (last) g_hf[idx] = h;
            __nv_bfloat16 hb = __float2bfloat16(h);
            __nv_bfloat16 lb = __float2bfloat16(h - __bfloat162float(hb));
            int mb = m >> 4, rowb = m & 15, kb = u >> 4, kk = u & 15;
            int lane2 = (rowb & 7) * 4 + ((kk & 7) >> 1);
            int reg = (rowb >> 3) + 2 * (kk >> 3);
            int half = kk & 1;
            size_t fo = ((size_t)(mb * 64 + kb)) * 512 + lane2 * 8 + reg * 2 + half;
            g_hf2[hwr + fo] = hb;
            g_hf2[hwr + fo + 256] = lb;
        }
    }
}

// ------------------ feature assembly + head MLPs ------------------
__global__ void k_feat(const float* __restrict__ head)
{
    int idx = blockIdx.x * blockDim.x + threadIdx.x;
    if (idx >= NB * FEATP) return;
    int b = idx / FEATP;
    int k = idx - b * FEATP;
    float v;
    if (k < 2)            v = head[b * 3 + 1 + k];
    else if (k < 1026)    v = g_c[b * NH + (k - 2)];
    else if (k < 2050)    v = g_hf[b * NH + (k - 1026)];
    else                  v = 0.f;
    g_feat[idx] = v;
}

__global__ __launch_bounds__(256) void k_head_gemm(
    const float* __restrict__ W3, const float* __restrict__ b3,
    const float* __restrict__ W4, const float* __restrict__ b4,
    const float* __restrict__ W5, const float* __restrict__ b5,
    const float* __restrict__ W6, const float* __restrict__ b6)
{
    const int which = blockIdx.z;
    const float* Wm = (which == 0) ? W3 : (which == 1) ? W4 : (which == 2) ? W5 : W6;
    const float* bv = (which == 0) ? b3 : (which == 1) ? b4 : (which == 2) ? b5 : b6;
    float* Cout = (which == 0) ? g_vlp : (which == 1) ? g_qlp : (which == 2) ? g_vle : g_qle;

    __shared__ float As[16][64];
    __shared__ float Bs[16][64];
    const int tid = threadIdx.x;
    const int tx = tid & 15;
    const int ty = tid >> 4;
    const int m0 = blockIdx.y * 64;
    const int n0 = blockIdx.x * 64;

    float acc[4][4];
#pragma unroll
    for (int i = 0; i < 4; ++i)
#pragma unroll
        for (int j = 0; j < 4; ++j) acc[i][j] = 0.f;

    const int KT = FEATP / 16;
    for (int kt = 0; kt < KT; ++kt) {
        const int kbase = kt * 16;
        {
            int idx = tid;
            int m  = idx >> 2;
            int k4 = (idx & 3) * 4;
            float4 v = *(const float4*)(g_feat + (size_t)(m0 + m) * FEATP + kbase + k4);
            As[k4 + 0][m] = v.x;
            As[k4 + 1][m] = v.y;
            As[k4 + 2][m] = v.z;
            As[k4 + 3][m] = v.w;
            int kb = idx >> 4;
            int nb = (idx & 15) * 4;
            int kg = kbase + kb;
            float4 w = make_float4(0.f, 0.f, 0.f, 0.f);
            if (kg < FEATR)
                w = *(const float4*)(Wm + (size_t)kg * 512 + n0 + nb);
            *(float4*)&Bs[kb][nb] = w;
        }
        __syncthreads();
#pragma unroll
        for (int kk = 0; kk < 16; ++kk) {
            float a[4], b[4];
            *(float4*)&a[0] = *(const float4*)&As[kk][ty * 4];
            *(float4*)&b[0] = *(const float4*)&Bs[kk][tx * 4];
#pragma unroll
            for (int i = 0; i < 4; ++i)
#pragma unroll
                for (int j = 0; j < 4; ++j)
                    acc[i][j] += a[i] * b[j];
        }
        __syncthreads();
    }

#pragma unroll
    for (int i = 0; i < 4; ++i) {
        int m = m0 + ty * 4 + i;
        int n = n0 + tx * 4;
        float4 r;
        r.x = acc[i][0] + bv[n + 0];
        r.y = acc[i][1] + bv[n + 1];
        r.z = acc[i][2] + bv[n + 2];
        r.w = acc[i][3] + bv[n + 3];
        r.x = r.x > 0.f ? r.x : 0.f;
        r.y = r.y > 0.f ? r.y : 0.f;
        r.z = r.z > 0.f ? r.z : 0.f;
        r.w = r.w > 0.f ? r.w : 0.f;
        *(float4*)(Cout + (size_t)m * 512 + n) = r;
    }
}

__global__ void k_combine(
    const float* __restrict__ head, const float* __restrict__ targetQ,
    const int* __restrict__ action,
    const float* __restrict__ Wsv, const float* __restrict__ bsv,
    const float* __restrict__ Wbv, const float* __restrict__ bbv,
    const float* __restrict__ Wsh, const float* __restrict__ bsh,
    const float* __restrict__ Wbh, const float* __restrict__ bbh,
    float* __restrict__ out, int out_size)
{
    const int b = blockIdx.x;
    const int tid = threadIdx.x;
    float s0 = 0.f, s1 = 0.f, s2 = 0.f, s3 = 0.f, s4 = 0.f, s5 = 0.f;
    for (int k = tid; k < 512; k += 128) {
        float vp = g_vlp[b * 512 + k];
        float qp = g_qlp[b * 512 + k];
        float ve = g_vle[b * 512 + k];
        float qe = g_qle[b * 512 + k];
        s0 += vp * Wsv[k];
        s1 += qp * Wsh[2 * k];
        s2 += qp * Wsh[2 * k + 1];
        s3 += ve * Wbv[k];
        s4 += qe * Wbh[2 * k];
        s5 += qe * Wbh[2 * k + 1];
    }
    __shared__ float red[6][128];
    red[0][tid] = s0; red[1][tid] = s1; red[2][tid] = s2;
    red[3][tid] = s3; red[4][tid] = s4; red[5][tid] = s5;
    __syncthreads();
    for (int off = 64; off > 0; off >>= 1) {
        if (tid < off) {
#pragma unroll
            for (int i = 0; i < 6; ++i) red[i][tid] += red[i][tid + off];
        }
        __syncthreads();
    }
    if (tid == 0) {
        float sellv = red[0][0] + bsv[0];
        float pa0 = red[1][0] + bsh[0];
        float pa1 = red[2][0] + bsh[1];
        float buyv = red[3][0] + bbv[0];
        float ea0 = red[4][0] + bbh[0];
        float ea1 = red[5][0] + bbh[1];
        float pm = 0.5f * (pa0 + pa1);
        float em = 0.5f * (ea0 + ea1);
        float pQ0 = pa0 - pm + sellv;
        float pQ1 = pa1 - pm + sellv;
        float eQ0 = ea0 - em + buyv;
        float eQ1 = ea1 - em + buyv;
        float isp = head[b * 3];
        float Q0, Q1;
        if (isp != 0.f) { Q0 = pQ0; Q1 = eQ1; }
        else            { Q0 = eQ0; Q1 = pQ1; }
        if (out_size >= 1 + 2 * NB) {
            out[1 + 2 * b]     = Q0;
            out[1 + 2 * b + 1] = Q1;
        }
        if (out_size >= 1 + 2 * NB + NB) {
            out[1 + 2 * NB + b] = (Q1 > Q0) ? 1.f : 0.f;
        }
        int a = action[b];
        float iv = (a == 0) ? Q0 : Q1;
        float d = targetQ[b] - iv;
        g_sq[b] = d * d;
    }
}

__global__ void k_loss(float* __restrict__ out, int out_size)
{
    __shared__ float r[256];
    int tid = threadIdx.x;
    r[tid] = g_sq[tid] + g_sq[tid + 256];
    __syncthreads();
    for (int off = 128; off > 0; off >>= 1) {
        if (tid < off) r[tid] += r[tid + off];
        __syncthreads();
    }
    if (tid == 0 && out_size >= 1) out[0] = r[0] * (1.f / 512.f);
}

// ------------------ launch ------------------
extern "C" void kernel_launch(void* const* d_in, const int* in_sizes, int n_in,
                              void* d_out, int out_size)
{
    const float* hist    = (const float*)d_in[0];
    const float* head    = (const float*)d_in[1];
    const float* targetQ = (const float*)d_in[2];
    const int*   action  = (const int*)d_in[3];
    const float* W_lstm  = (const float*)d_in[4];
    const float* b_lstm  = (const float*)d_in[5];
    const float* W3 = (const float*)d_in[6],  *b3 = (const float*)d_in[7];
    const float* W4 = (const float*)d_in[8],  *b4 = (const float*)d_in[9];
    const float* W5 = (const float*)d_in[10], *b5 = (const float*)d_in[11];
    const float* W6 = (const float*)d_in[12], *b6 = (const float*)d_in[13];
    const float* Wsv = (const float*)d_in[14], *bsv = (const float*)d_in[15];
    const float* Wbv = (const float*)d_in[16], *bbv = (const float*)d_in[17];
    const float* Wsh = (const float*)d_in[18], *bsh = (const float*)d_in[19];
    const float* Wbh = (const float*)d_in[20], *bbh = (const float*)d_in[21];
    float* out = (float*)d_out;

    k_init<<<(NB * NH * 2 + 255) / 256, 256>>>();
    k_prep_w<<<((size_t)NZ * KTOT + 255) / 256, 256>>>(W_lstm);
    k_prep_x<<<((size_t)NB * NT * NF + 255) / 256, 256>>>(hist);

    dim3 gl(128, 4);  // 512 CTAs, 3 CTAs/SM, no smem, no barriers
    for (int t = 0; t < NT; ++t)
        k_step<<<gl, 256>>>(b_lstm, t);

    k_feat<<<(NB * FEATP + 255) / 256, 256>>>(head);

    dim3 gh(8, 8, 4);
    k_head_gemm<<<gh, 256>>>(W3, b3, W4, b4, W5, b5, W6, b6);

    k_combine<<<NB, 128>>>(head, targetQ, action,
                           Wsv, bsv, Wbv, bbv, Wsh, bsh, Wbh, bbh,
                           out, out_size);
    k_loss<<<1, 256>>>(out, out_size);
}

// round 13
// speedup vs baseline: 1.0046x; 1.0046x over previous
#include <cuda_runtime.h>
#include <cuda_bf16.h>
#include <cstdint>

#define NB 512      // batch
#define NT 256      // time steps
#define NF 128      // features
#define NH 1024     // hidden
#define NZ 4096     // 4*H
#define KTOT 1152   // NF + NH
#define FEATP 2064  // padded feature length
#define FEATR 2050  // real feature length
#define NCTA 256u   // persistent grid size

// ------------------ device scratch (no allocation allowed) ------------------
// Fragment-layout arrays, hi/lo interleaved per 1KB block: [hi 512B][lo 512B].
__device__ __align__(16) __nv_bfloat16 g_Wf[(size_t)NZ * KTOT * 2];      // W^T frag blocks [J][72]
__device__ __align__(16) __nv_bfloat16 g_xf[(size_t)NB * NT * NF * 2];   // x frag blocks [mb][NT][8]
__device__ __align__(16) __nv_bfloat16 g_hf2[2 * (size_t)NB * NH * 2];   // h frag blocks [buf][mb][64]
__device__ float g_c[NB * NH];
__device__ float g_hf[NB * NH];
__device__ float g_feat[NB * FEATP];
__device__ float g_vlp[NB * 512];
__device__ float g_qlp[NB * 512];
__device__ float g_vle[NB * 512];
__device__ float g_qle[NB * 512];
__device__ float g_sq[NB];
__device__ unsigned g_bar;      // grid barrier counter (reset by k_init each launch)

// ------------------ helpers ------------------
#define MMA16816(d, a, b) \
    asm volatile("mma.sync.aligned.m16n8k16.row.col.f32.bf16.bf16.f32 " \
                 "{%0,%1,%2,%3}, {%4,%5,%6,%7}, {%8,%9}, {%0,%1,%2,%3};" \
                 : "+f"((d)[0]), "+f"((d)[1]), "+f"((d)[2]), "+f"((d)[3]) \
                 : "r"((a)[0]), "r"((a)[1]), "r"((a)[2]), "r"((a)[3]), \
                   "r"((b)[0]), "r"((b)[1]))

__device__ __forceinline__ uint4 ldg_cg(const __nv_bfloat16* p)
{
    uint4 v;
    asm volatile("ld.global.cg.v4.u32 {%0,%1,%2,%3}, [%4];"
                 : "=r"(v.x), "=r"(v.y), "=r"(v.z), "=r"(v.w) : "l"(p));
    return v;
}

__device__ __forceinline__ float fsig(float x)
{
    float e = __expf(-x);
    return __fdividef(1.f, 1.f + e);
}
__device__ __forceinline__ float ftanh(float x)
{
    float e = __expf(2.f * x);
    return 1.f - __fdividef(2.f, e + 1.f);
}

// ------------------ prep kernels ------------------
__global__ void k_init()
{
    int i = blockIdx.x * blockDim.x + threadIdx.x;
    if (i == 0) g_bar = 0u;
    if (i < NB * NH) g_c[i] = 0.f;
    if (i < NB * NH * 2) g_hf2[i] = __float2bfloat16(0.f);   // h buffer 0
}

// W -> permuted (col j = u*4+gate), split hi/lo, B-fragment layout, hi/lo interleaved blocks.
__global__ void k_prep_w(const float* __restrict__ W)
{
    int id = blockIdx.x * blockDim.x + threadIdx.x;
    if (id >= NZ * KTOT) return;
    int j = id / KTOT;
    int k = id - j * KTOT;
    int u = j >> 2;
    int g = j & 3;
    float w = W[(size_t)k * NZ + g * NH + u];
    __nv_bfloat16 hi = __float2bfloat16(w);
    float lo = w - __bfloat162float(hi);
    int J = j >> 4;
    int n16 = j & 15;
    int K16 = k >> 4;
    int kk = k & 15;
    int lane = (n16 & 7) * 4 + ((kk & 7) >> 1);
    int reg = (n16 >> 3) * 2 + (kk >> 3);
    int half = kk & 1;
    size_t out = ((size_t)J * 72 + K16) * 512 + lane * 8 + reg * 2 + half;
    g_Wf[out] = hi;
    g_Wf[out + 256] = __float2bfloat16(lo);
}

// history -> split hi/lo, A-fragment layout, hi/lo interleaved blocks [mb][t][kb].
__global__ void k_prep_x(const float* __restrict__ hist)
{
    int id = blockIdx.x * blockDim.x + threadIdx.x;
    if (id >= NB * NT * NF) return;
    int b = id / (NT * NF);
    int r = id - b * (NT * NF);
    int t = r / NF;
    int f = r - t * NF;
    float v = hist[id];
    __nv_bfloat16 hi = __float2bfloat16(v);
    float lo = v - __bfloat162float(hi);
    int mb = b >> 4, row = b & 15;
    int kb = f >> 4, kk = f & 15;
    int lane = (row & 7) * 4 + ((kk & 7) >> 1);
    int reg = (row >> 3) + 2 * (kk >> 3);
    int half = kk & 1;
    size_t out = ((size_t)(mb * NT + t) * 8 + kb) * 512 + lane * 8 + reg * 2 + half;
    g_xf[out] = hi;
    g_xf[out + 256] = __float2bfloat16(lo);
}

// ------------------ persistent fused LSTM: all 256 steps in ONE kernel ------------------
// grid (64 n-tiles, 4 m-tiles) = 256 CTAs, 2/SM (all co-resident: 256 <= 2*148).
// 256 threads (8 warps, 4m x 2n, warp tile 32m x 32n). No smem. Steps separated by a
// monotonic atomic grid barrier. h loads use ld.global.cg (L2) because L1 is NOT
// coherent with peer-SM writes within one launch. x/W loads stay L1-cached (written
// by earlier launches). Cross-step prefetch: A slices 0,1 (pure x) and B slices 0,1,2
// (W, t-invariant) are issued before the barrier to hide the step ramp.
__global__ __launch_bounds__(256, 2) void k_lstm(const float* __restrict__ blstm)
{
    const int tid = threadIdx.x;
    const int wid = tid >> 5;
    const int lane = tid & 31;
    const int ntile = blockIdx.x;      // 0..63
    const int mtile = blockIdx.y;      // 0..3
    const int wm = wid & 3;
    const int wn = wid >> 2;
    const int u0 = ntile * 16;
    const int m0 = mtile * 128;

    const size_t HB = (size_t)NB * NH * 2;
    const int mbG0 = mtile * 8 + wm * 2;
    const int J0 = ntile * 4 + wn * 2;

    const __nv_bfloat16* pX0 = g_xf + ((size_t)(mbG0 * NT) * 8) * 512 + lane * 8;
    const __nv_bfloat16* pH0 = g_hf2 + ((size_t)mbG0 * 64) * 512 + lane * 8;
    const __nv_bfloat16* pH1 = pH0 + HB;
    const __nv_bfloat16* pB = g_Wf + ((size_t)J0 * 72) * 512 + lane * 8;

    const size_t XMT = (size_t)NT * 8 * 512;   // x mt stride (elems)
    const size_t HMT = (size_t)64 * 512;       // h mt stride
    const size_t BNP = (size_t)72 * 512;       // B np stride

    uint4 Ah[2][2], Al[2][2];   // [buf][mt]
    uint4 Bh[3][2], Bl[3][2];   // [buf][np]

    auto ldAx = [&](const __nv_bfloat16* pX, int s, int buf) {   // x slices (0..7), L1 ok
        const __nv_bfloat16* base = pX + (size_t)s * 512;
        Ah[buf][0] = *(const uint4*)(base);
        Al[buf][0] = *(const uint4*)(base + 256);
        Ah[buf][1] = *(const uint4*)(base + XMT);
        Al[buf][1] = *(const uint4*)(base + XMT + 256);
    };
    auto ldAh = [&](const __nv_bfloat16* pH, int s, int buf) {   // h slices (8..71), L2 only
        const __nv_bfloat16* base = pH + (size_t)(s - 8) * 512;
        Ah[buf][0] = ldg_cg(base);
        Al[buf][0] = ldg_cg(base + 256);
        Ah[buf][1] = ldg_cg(base + HMT);
        Al[buf][1] = ldg_cg(base + HMT + 256);
    };
    auto ldB = [&](int s, int buf) {
        const __nv_bfloat16* base = pB + (size_t)s * 512;
        Bh[buf][0] = *(const uint4*)(base);
        Bl[buf][0] = *(const uint4*)(base + 256);
        Bh[buf][1] = *(const uint4*)(base + BNP);
        Bl[buf][1] = *(const uint4*)(base + BNP + 256);
    };

    float acc[2][4][4];

    auto domma = [&](int ia, int ib) {
        // term-major: hh, hl, lh (identical accumulation order to rounds 9/10)
#pragma unroll
        for (int mt = 0; mt < 2; ++mt)
#pragma unroll
            for (int nt = 0; nt < 4; ++nt)
                MMA16816(acc[mt][nt], ((uint32_t*)&Ah[ia][mt]),
                         ((uint32_t*)&Bh[ib][nt >> 1]) + (nt & 1) * 2);
#pragma unroll
        for (int mt = 0; mt < 2; ++mt)
#pragma unroll
            for (int nt = 0; nt < 4; ++nt)
                MMA16816(acc[mt][nt], ((uint32_t*)&Ah[ia][mt]),
                         ((uint32_t*)&Bl[ib][nt >> 1]) + (nt & 1) * 2);
#pragma unroll
        for (int mt = 0; mt < 2; ++mt)
#pragma unroll
            for (int nt = 0; nt < 4; ++nt)
                MMA16816(acc[mt][nt], ((uint32_t*)&Al[ia][mt]),
                         ((uint32_t*)&Bh[ib][nt >> 1]) + (nt & 1) * 2);
    };

    const int g = lane >> 2;
    const int tq = lane & 3;
    const bool even = (tq & 1) == 0;

    // prologue: preload for t = 0 (x + W only, h not needed until slice 8)
    ldAx(pX0, 0, 0);
    ldB(0, 0);
    ldAx(pX0, 1, 1);
    ldB(1, 1);
    ldB(2, 2);

    for (int t = 0; t < NT; ++t) {
        const __nv_bfloat16* pX = pX0 + (size_t)t * 4096;
        const __nv_bfloat16* pH = (t & 1) ? pH1 : pH0;
        const size_t hwr = ((t + 1) & 1) ? HB : 0;

#pragma unroll
        for (int a = 0; a < 2; ++a)
#pragma unroll
            for (int b = 0; b < 4; ++b)
#pragma unroll
                for (int cc = 0; cc < 4; ++cc) acc[a][b][cc] = 0.f;

#pragma unroll 1
        for (int s = 0; s < 72; s += 6) {
#pragma unroll
            for (int i = 0; i < 6; ++i) {
                const int q = s + i;
                domma(i & 1, i % 3);
                if (q + 2 < 72) {
                    if (q + 2 < 8) ldAx(pX, q + 2, i & 1);
                    else           ldAh(pH, q + 2, i & 1);
                }
                if (q + 3 < 72) ldB(q + 3, i % 3);
            }
        }

        // ---- fused cell epilogue ----
        const bool last = (t == NT - 1);
#pragma unroll
        for (int mt = 0; mt < 2; ++mt) {
#pragma unroll
            for (int nt = 0; nt < 4; ++nt) {
                float c0 = acc[mt][nt][0], c1 = acc[mt][nt][1];
                float c2 = acc[mt][nt][2], c3 = acc[mt][nt][3];
                float s0 = even ? c2 : c0;
                float s1 = even ? c3 : c1;
                float r0 = __shfl_xor_sync(0xffffffffu, s0, 1);
                float r1 = __shfl_xor_sync(0xffffffffu, s1, 1);
                float zi, zj, zf, zo;
                int row;
                if (even) { row = g;     zi = c0; zj = c1; zf = r0; zo = r1; }
                else      { row = g + 8; zi = r0; zj = r1; zf = c2; zo = c3; }
                int u = u0 + wn * 8 + nt * 2 + (tq >> 1);
                int m = m0 + wm * 32 + mt * 16 + row;
                float bi = blstm[u];
                float bj = blstm[NH + u];
                float bf_ = blstm[2 * NH + u];
                float bo = blstm[3 * NH + u];
                size_t idx = (size_t)m * NH + u;
                float cold = g_c[idx];
                float cn = fsig(zf + bf_ + 1.f) * cold + fsig(zi + bi) * ftanh(zj + bj);
                float h = fsig(zo + bo) * ftanh(cn);
                g_c[idx] = cn;
                if (last) g_hf[idx] = h;
                __nv_bfloat16 hb = __float2bfloat16(h);
                __nv_bfloat16 lb = __float2bfloat16(h - __bfloat162float(hb));
                int mb = m >> 4, rowb = m & 15, kb = u >> 4, kk = u & 15;
                int lane2 = (rowb & 7) * 4 + ((kk & 7) >> 1);
                int reg = (rowb >> 3) + 2 * (kk >> 3);
                int half = kk & 1;
                size_t fo = ((size_t)(mb * 64 + kb)) * 512 + lane2 * 8 + reg * 2 + half;
                g_hf2[hwr + fo] = hb;
                g_hf2[hwr + fo + 256] = lb;
            }
        }

        // preload next step's x/W slices (h-independent) BEFORE the barrier
        if (t + 1 < NT) {
            const __nv_bfloat16* pXn = pX + 4096;
            ldAx(pXn, 0, 0);
            ldB(0, 0);
            ldAx(pXn, 1, 1);
            ldB(1, 1);
            ldB(2, 2);
        }

        // ---- grid barrier (monotonic counter) ----
        __threadfence();
        __syncthreads();
        if (tid == 0) {
            atomicAdd(&g_bar, 1u);
            const unsigned tgt = NCTA * (unsigned)(t + 1);
            while (*(volatile unsigned*)&g_bar < tgt) __nanosleep(64);
        }
        __syncthreads();
    }
}

// ------------------ feature assembly + head MLPs ------------------
__global__ void k_feat(const float* __restrict__ head)
{
    int idx = blockIdx.x * blockDim.x + threadIdx.x;
    if (idx >= NB * FEATP) return;
    int b = idx / FEATP;
    int k = idx - b * FEATP;
    float v;
    if (k < 2)            v = head[b * 3 + 1 + k];
    else if (k < 1026)    v = g_c[b * NH + (k - 2)];
    else if (k < 2050)    v = g_hf[b * NH + (k - 1026)];
    else                  v = 0.f;
    g_feat[idx] = v;
}

__global__ __launch_bounds__(256) void k_head_gemm(
    const float* __restrict__ W3, const float* __restrict__ b3,
    const float* __restrict__ W4, const float* __restrict__ b4,
    const float* __restrict__ W5, const float* __restrict__ b5,
    const float* __restrict__ W6, const float* __restrict__ b6)
{
    const int which = blockIdx.z;
    const float* Wm = (which == 0) ? W3 : (which == 1) ? W4 : (which == 2) ? W5 : W6;
    const float* bv = (which == 0) ? b3 : (which == 1) ? b4 : (which == 2) ? b5 : b6;
    float* Cout = (which == 0) ? g_vlp : (which == 1) ? g_qlp : (which == 2) ? g_vle : g_qle;

    __shared__ float As[16][64];
    __shared__ float Bs[16][64];
    const int tid = threadIdx.x;
    const int tx = tid & 15;
    const int ty = tid >> 4;
    const int m0 = blockIdx.y * 64;
    const int n0 = blockIdx.x * 64;

    float acc[4][4];
#pragma unroll
    for (int i = 0; i < 4; ++i)
#pragma unroll
        for (int j = 0; j < 4; ++j) acc[i][j] = 0.f;

    const int KT = FEATP / 16;
    for (int kt = 0; kt < KT; ++kt) {
        const int kbase = kt * 16;
        {
            int idx = tid;
            int m  = idx >> 2;
            int k4 = (idx & 3) * 4;
            float4 v = *(const float4*)(g_feat + (size_t)(m0 + m) * FEATP + kbase + k4);
            As[k4 + 0][m] = v.x;
            As[k4 + 1][m] = v.y;
            As[k4 + 2][m] = v.z;
            As[k4 + 3][m] = v.w;
            int kb = idx >> 4;
            int nb = (idx & 15) * 4;
            int kg = kbase + kb;
            float4 w = make_float4(0.f, 0.f, 0.f, 0.f);
            if (kg < FEATR)
                w = *(const float4*)(Wm + (size_t)kg * 512 + n0 + nb);
            *(float4*)&Bs[kb][nb] = w;
        }
        __syncthreads();
#pragma unroll
        for (int kk = 0; kk < 16; ++kk) {
            float a[4], b[4];
            *(float4*)&a[0] = *(const float4*)&As[kk][ty * 4];
            *(float4*)&b[0] = *(const float4*)&Bs[kk][tx * 4];
#pragma unroll
            for (int i = 0; i < 4; ++i)
#pragma unroll
                for (int j = 0; j < 4; ++j)
                    acc[i][j] += a[i] * b[j];
        }
        __syncthreads();
    }

#pragma unroll
    for (int i = 0; i < 4; ++i) {
        int m = m0 + ty * 4 + i;
        int n = n0 + tx * 4;
        float4 r;
        r.x = acc[i][0] + bv[n + 0];
        r.y = acc[i][1] + bv[n + 1];
        r.z = acc[i][2] + bv[n + 2];
        r.w = acc[i][3] + bv[n + 3];
        r.x = r.x > 0.f ? r.x : 0.f;
        r.y = r.y > 0.f ? r.y : 0.f;
        r.z = r.z > 0.f ? r.z : 0.f;
        r.w = r.w > 0.f ? r.w : 0.f;
        *(float4*)(Cout + (size_t)m * 512 + n) = r;
    }
}

__global__ void k_combine(
    const float* __restrict__ head, const float* __restrict__ targetQ,
    const int* __restrict__ action,
    const float* __restrict__ Wsv, const float* __restrict__ bsv,
    const float* __restrict__ Wbv, const float* __restrict__ bbv,
    const float* __restrict__ Wsh, const float* __restrict__ bsh,
    const float* __restrict__ Wbh, const float* __restrict__ bbh,
    float* __restrict__ out, int out_size)
{
    const int b = blockIdx.x;
    const int tid = threadIdx.x;
    float s0 = 0.f, s1 = 0.f, s2 = 0.f, s3 = 0.f, s4 = 0.f, s5 = 0.f;
    for (int k = tid; k < 512; k += 128) {
        float vp = g_vlp[b * 512 + k];
        float qp = g_qlp[b * 512 + k];
        float ve = g_vle[b * 512 + k];
        float qe = g_qle[b * 512 + k];
        s0 += vp * Wsv[k];
        s1 += qp * Wsh[2 * k];
        s2 += qp * Wsh[2 * k + 1];
        s3 += ve * Wbv[k];
        s4 += qe * Wbh[2 * k];
        s5 += qe * Wbh[2 * k + 1];
    }
    __shared__ float red[6][128];
    red[0][tid] = s0; red[1][tid] = s1; red[2][tid] = s2;
    red[3][tid] = s3; red[4][tid] = s4; red[5][tid] = s5;
    __syncthreads();
    for (int off = 64; off > 0; off >>= 1) {
        if (tid < off) {
#pragma unroll
            for (int i = 0; i < 6; ++i) red[i][tid] += red[i][tid + off];
        }
        __syncthreads();
    }
    if (tid == 0) {
        float sellv = red[0][0] + bsv[0];
        float pa0 = red[1][0] + bsh[0];
        float pa1 = red[2][0] + bsh[1];
        float buyv = red[3][0] + bbv[0];
        float ea0 = red[4][0] + bbh[0];
        float ea1 = red[5][0] + bbh[1];
        float pm = 0.5f * (pa0 + pa1);
        float em = 0.5f * (ea0 + ea1);
        float pQ0 = pa0 - pm + sellv;
        float pQ1 = pa1 - pm + sellv;
        float eQ0 = ea0 - em + buyv;
        float eQ1 = ea1 - em + buyv;
        float isp = head[b * 3];
        float Q0, Q1;
        if (isp != 0.f) { Q0 = pQ0; Q1 = eQ1; }
        else            { Q0 = eQ0; Q1 = pQ1; }
        if (out_size >= 1 + 2 * NB) {
            out[1 + 2 * b]     = Q0;
            out[1 + 2 * b + 1] = Q1;
        }
        if (out_size >= 1 + 2 * NB + NB) {
            out[1 + 2 * NB + b] = (Q1 > Q0) ? 1.f : 0.f;
        }
        int a = action[b];
        float iv = (a == 0) ? Q0 : Q1;
        float d = targetQ[b] - iv;
        g_sq[b] = d * d;
    }
}

__global__ void k_loss(float* __restrict__ out, int out_size)
{
    __shared__ float r[256];
    int tid = threadIdx.x;
    r[tid] = g_sq[tid] + g_sq[tid + 256];
    __syncthreads();
    for (int off = 128; off > 0; off >>= 1) {
        if (tid < off) r[tid] += r[tid + off];
        __syncthreads();
    }
    if (tid == 0 && out_size >= 1) out[0] = r[0] * (1.f / 512.f);
}

// ------------------ launch ------------------
extern "C" void kernel_launch(void* const* d_in, const int* in_sizes, int n_in,
                              void* d_out, int out_size)
{
    const float* hist    = (const float*)d_in[0];
    const float* head    = (const float*)d_in[1];
    const float* targetQ = (const float*)d_in[2];
    const int*   action  = (const int*)d_in[3];
    const float* W_lstm  = (const float*)d_in[4];
    const float* b_lstm  = (const float*)d_in[5];
    const float* W3 = (const float*)d_in[6],  *b3 = (const float*)d_in[7];
    const float* W4 = (const float*)d_in[8],  *b4 = (const float*)d_in[9];
    const float* W5 = (const float*)d_in[10], *b5 = (const float*)d_in[11];
    const float* W6 = (const float*)d_in[12], *b6 = (const float*)d_in[13];
    const float* Wsv = (const float*)d_in[14], *bsv = (const float*)d_in[15];
    const float* Wbv = (const float*)d_in[16], *bbv = (const float*)d_in[17];
    const float* Wsh = (const float*)d_in[18], *bsh = (const float*)d_in[19];
    const float* Wbh = (const float*)d_in[20], *bbh = (const float*)d_in[21];
    float* out = (float*)d_out;

    k_init<<<(NB * NH * 2 + 255) / 256, 256>>>();
    k_prep_w<<<((size_t)NZ * KTOT + 255) / 256, 256>>>(W_lstm);
    k_prep_x<<<((size_t)NB * NT * NF + 255) / 256, 256>>>(hist);

    dim3 gl(64, 4);  // 256 CTAs, 2/SM, all resident — single persistent kernel
    k_lstm<<<gl, 256>>>(b_lstm);

    k_feat<<<(NB * FEATP + 255) / 256, 256>>>(head);

    dim3 gh(8, 8, 4);
    k_head_gemm<<<gh, 256>>>(W3, b3, W4, b4, W5, b5, W6, b6);

    k_combine<<<NB, 128>>>(head, targetQ, action,
                           Wsv, bsv, Wbv, bbv, Wsh, bsh, Wbh, bbh,
                           out, out_size);
    k_loss<<<1, 256>>>(out, out_size);
}

// round 15
// speedup vs baseline: 1.1106x; 1.1056x over previous
#include <cuda_runtime.h>
#include <cuda_bf16.h>
#include <cstdint>

#define NB 512      // batch
#define NT 256      // time steps
#define NF 128      // features
#define NH 1024     // hidden
#define NZ 4096     // 4*H
#define KTOT 1152   // NF + NH
#define FEATP 2064  // padded feature length
#define FEATR 2050  // real feature length

// ------------------ device scratch (no allocation allowed) ------------------
// Fragment-layout arrays. Per-lane hi/lo interleave inside each 1KB slice block:
// element offset = lane*16 + sel*8 + reg*2 + half  (sel: 0=hi, 1=lo)
// -> one 32B load at byte offset lane*32 returns the 16B hi frag + 16B lo frag.
__device__ __align__(32) __nv_bfloat16 g_Wf[(size_t)NZ * KTOT * 2];      // W^T frag blocks [J][72]
__device__ __align__(32) __nv_bfloat16 g_xf[(size_t)NB * NT * NF * 2];   // x frag blocks [mb][NT][8]
__device__ __align__(32) __nv_bfloat16 g_hf2[2 * (size_t)NB * NH * 2];   // h frag blocks [buf][mb][64]
__device__ float g_c[NB * NH];
__device__ float g_hf[NB * NH];
__device__ float g_feat[NB * FEATP];
__device__ float g_vlp[NB * 512];
__device__ float g_qlp[NB * 512];
__device__ float g_vle[NB * 512];
__device__ float g_qle[NB * 512];
__device__ float g_sq[NB];

// ------------------ helpers ------------------
#define MMA16816(d, a, b) \
    asm volatile("mma.sync.aligned.m16n8k16.row.col.f32.bf16.bf16.f32 " \
                 "{%0,%1,%2,%3}, {%4,%5,%6,%7}, {%8,%9}, {%0,%1,%2,%3};" \
                 : "+f"((d)[0]), "+f"((d)[1]), "+f"((d)[2]), "+f"((d)[3]) \
                 : "r"((a)[0]), "r"((a)[1]), "r"((a)[2]), "r"((a)[3]), \
                   "r"((b)[0]), "r"((b)[1]))

// 256-bit loads (required width for L2 eviction-policy hints on this target).
__device__ __forceinline__ void ldg_el8(const __nv_bfloat16* p, uint4& h, uint4& l)
{
    asm volatile("ld.global.L2::evict_last.v8.b32 {%0,%1,%2,%3,%4,%5,%6,%7}, [%8];"
                 : "=r"(h.x), "=r"(h.y), "=r"(h.z), "=r"(h.w),
                   "=r"(l.x), "=r"(l.y), "=r"(l.z), "=r"(l.w) : "l"(p));
}
__device__ __forceinline__ void ldg_ef8(const __nv_bfloat16* p, uint4& h, uint4& l)
{
    asm volatile("ld.global.L2::evict_first.v8.b32 {%0,%1,%2,%3,%4,%5,%6,%7}, [%8];"
                 : "=r"(h.x), "=r"(h.y), "=r"(h.z), "=r"(h.w),
                   "=r"(l.x), "=r"(l.y), "=r"(l.z), "=r"(l.w) : "l"(p));
}
__device__ __forceinline__ void ldg_v8(const __nv_bfloat16* p, uint4& h, uint4& l)
{
    asm volatile("ld.global.v8.b32 {%0,%1,%2,%3,%4,%5,%6,%7}, [%8];"
                 : "=r"(h.x), "=r"(h.y), "=r"(h.z), "=r"(h.w),
                   "=r"(l.x), "=r"(l.y), "=r"(l.z), "=r"(l.w) : "l"(p));
}

__device__ __forceinline__ float fsig(float x)
{
    float e = __expf(-x);
    return __fdividef(1.f, 1.f + e);
}
__device__ __forceinline__ float ftanh(float x)
{
    float e = __expf(2.f * x);
    return 1.f - __fdividef(2.f, e + 1.f);
}

// ------------------ prep kernels ------------------
__global__ void k_init()
{
    int i = blockIdx.x * blockDim.x + threadIdx.x;
    if (i < NB * NH) g_c[i] = 0.f;
    if (i < NB * NH * 2) g_hf2[i] = __float2bfloat16(0.f);   // h buffer 0
}

// W -> permuted (col j = u*4+gate), split hi/lo, B-fragment layout, per-lane hi/lo interleave.
__global__ void k_prep_w(const float* __restrict__ W)
{
    int id = blockIdx.x * blockDim.x + threadIdx.x;
    if (id >= NZ * KTOT) return;
    int j = id / KTOT;
    int k = id - j * KTOT;
    int u = j >> 2;
    int g = j & 3;
    float w = W[(size_t)k * NZ + g * NH + u];
    __nv_bfloat16 hi = __float2bfloat16(w);
    float lo = w - __bfloat162float(hi);
    int J = j >> 4;
    int n16 = j & 15;
    int K16 = k >> 4;
    int kk = k & 15;
    int lane = (n16 & 7) * 4 + ((kk & 7) >> 1);
    int reg = (n16 >> 3) * 2 + (kk >> 3);
    int half = kk & 1;
    size_t out = ((size_t)J * 72 + K16) * 512 + lane * 16 + reg * 2 + half;
    g_Wf[out] = hi;
    g_Wf[out + 8] = __float2bfloat16(lo);
}

// history -> split hi/lo, A-fragment layout, per-lane hi/lo interleave, blocks [mb][t][kb].
__global__ void k_prep_x(const float* __restrict__ hist)
{
    int id = blockIdx.x * blockDim.x + threadIdx.x;
    if (id >= NB * NT * NF) return;
    int b = id / (NT * NF);
    int r = id - b * (NT * NF);
    int t = r / NF;
    int f = r - t * NF;
    float v = hist[id];
    __nv_bfloat16 hi = __float2bfloat16(v);
    float lo = v - __bfloat162float(hi);
    int mb = b >> 4, row = b & 15;
    int kb = f >> 4, kk = f & 15;
    int lane = (row & 7) * 4 + ((kk & 7) >> 1);
    int reg = (row >> 3) + 2 * (kk >> 3);
    int half = kk & 1;
    size_t out = ((size_t)(mb * NT + t) * 8 + kb) * 512 + lane * 16 + reg * 2 + half;
    g_xf[out] = hi;
    g_xf[out + 8] = __float2bfloat16(lo);
}

// ------------------ fused LSTM step: smem-free fragment-direct GEMM + cell ------------------
// grid (64 n-tiles, 4 m-tiles), 256 threads (8 warps, 4m x 2n, warp 32m x 32n).
// No smem, no barriers. A prefetch depth 2, B depth 3. K loop unrolled by 6.
// 256-bit loads: one ld.v8 returns hi+lo frags. Cache policy: W = L2 evict_last
// (resident across all 256 steps), x = evict_first (single-use stream), h = default.
__global__ __launch_bounds__(256, 2) void k_step(const float* __restrict__ blstm, int t)
{
    const int tid = threadIdx.x;
    const int wid = tid >> 5;
    const int lane = tid & 31;
    const int ntile = blockIdx.x;
    const int mtile = blockIdx.y;
    const int wm = wid & 3;
    const int wn = wid >> 2;
    const int u0 = ntile * 16;
    const int m0 = mtile * 128;

    const size_t HB = (size_t)NB * NH * 2;
    const size_t hrd = (size_t)(t & 1) * HB;
    const size_t hwr = (size_t)((t + 1) & 1) * HB;

    float acc[2][4][4];
#pragma unroll
    for (int a = 0; a < 2; ++a)
#pragma unroll
        for (int b = 0; b < 4; ++b)
#pragma unroll
            for (int cc = 0; cc < 4; ++cc) acc[a][b][cc] = 0.f;

    const int mbG0 = mtile * 8 + wm * 2;
    const int J0 = ntile * 4 + wn * 2;

    const __nv_bfloat16* pX = g_xf + ((size_t)(mbG0 * NT + t) * 8) * 512 + lane * 16;
    const __nv_bfloat16* pH = g_hf2 + hrd + ((size_t)mbG0 * 64) * 512 + lane * 16;
    const __nv_bfloat16* pB = g_Wf + ((size_t)J0 * 72) * 512 + lane * 16;

    const size_t XMT = (size_t)NT * 8 * 512;   // x mt stride (elems)
    const size_t HMT = (size_t)64 * 512;       // h mt stride
    const size_t BNP = (size_t)72 * 512;       // B np stride

    uint4 Ah[2][2], Al[2][2];   // [buf][mt]
    uint4 Bh[3][2], Bl[3][2];   // [buf][np]

    auto ldA = [&](int s, int buf) {
        if (s < 8) {
            const __nv_bfloat16* base = pX + (size_t)s * 512;
            ldg_ef8(base,       Ah[buf][0], Al[buf][0]);
            ldg_ef8(base + XMT, Ah[buf][1], Al[buf][1]);
        } else {
            const __nv_bfloat16* base = pH + (size_t)(s - 8) * 512;
            ldg_v8(base,       Ah[buf][0], Al[buf][0]);
            ldg_v8(base + HMT, Ah[buf][1], Al[buf][1]);
        }
    };
    auto ldB = [&](int s, int buf) {
        const __nv_bfloat16* base = pB + (size_t)s * 512;
        ldg_el8(base,       Bh[buf][0], Bl[buf][0]);
        ldg_el8(base + BNP, Bh[buf][1], Bl[buf][1]);
    };

    auto domma = [&](int ia, int ib) {
        // term-major: hh, hl, lh (identical accumulation order to rounds 9/10)
#pragma unroll
        for (int mt = 0; mt < 2; ++mt)
#pragma unroll
            for (int nt = 0; nt < 4; ++nt)
                MMA16816(acc[mt][nt], ((uint32_t*)&Ah[ia][mt]),
                         ((uint32_t*)&Bh[ib][nt >> 1]) + (nt & 1) * 2);
#pragma unroll
        for (int mt = 0; mt < 2; ++mt)
#pragma unroll
            for (int nt = 0; nt < 4; ++nt)
                MMA16816(acc[mt][nt], ((uint32_t*)&Ah[ia][mt]),
                         ((uint32_t*)&Bl[ib][nt >> 1]) + (nt & 1) * 2);
#pragma unroll
        for (int mt = 0; mt < 2; ++mt)
#pragma unroll
            for (int nt = 0; nt < 4; ++nt)
                MMA16816(acc[mt][nt], ((uint32_t*)&Al[ia][mt]),
                         ((uint32_t*)&Bh[ib][nt >> 1]) + (nt & 1) * 2);
    };

    ldA(0, 0);
    ldB(0, 0);
    ldA(1, 1);
    ldB(1, 1);
    ldB(2, 2);

#pragma unroll 1
    for (int s = 0; s < 72; s += 6) {
#pragma unroll
        for (int i = 0; i < 6; ++i) {
            const int q = s + i;
            domma(i & 1, i % 3);
            if (q + 2 < 72) ldA(q + 2, i & 1);
            if (q + 3 < 72) ldB(q + 3, i % 3);
        }
    }

    // ---- fused cell epilogue (register accumulators) ----
    const int g = lane >> 2;
    const int tq = lane & 3;
    const bool even = (tq & 1) == 0;
    const bool last = (t == NT - 1);
#pragma unroll
    for (int mt = 0; mt < 2; ++mt) {
#pragma unroll
        for (int nt = 0; nt < 4; ++nt) {
            float c0 = acc[mt][nt][0], c1 = acc[mt][nt][1];
            float c2 = acc[mt][nt][2], c3 = acc[mt][nt][3];
            float s0 = even ? c2 : c0;
            float s1 = even ? c3 : c1;
            float r0 = __shfl_xor_sync(0xffffffffu, s0, 1);
            float r1 = __shfl_xor_sync(0xffffffffu, s1, 1);
            float zi, zj, zf, zo;
            int row;
            if (even) { row = g;     zi = c0; zj = c1; zf = r0; zo = r1; }
            else      { row = g + 8; zi = r0; zj = r1; zf = c2; zo = c3; }
            int u = u0 + wn * 8 + nt * 2 + (tq >> 1);
            int m = m0 + wm * 32 + mt * 16 + row;
            float bi = blstm[u];
            float bj = blstm[NH + u];
            float bf_ = blstm[2 * NH + u];
            float bo = blstm[3 * NH + u];
            size_t idx = (size_t)m * NH + u;
            float cold = g_c[idx];
            float cn = fsig(zf + bf_ + 1.f) * cold + fsig(zi + bi) * ftanh(zj + bj);
            float h = fsig(zo + bo) * ftanh(cn);
            g_c[idx] = cn;
            if (last) g_hf[idx] = h;
            __nv_bfloat16 hb = __float2bfloat16(h);
            __nv_bfloat16 lb = __float2bfloat16(h - __bfloat162float(hb));
            int mb = m >> 4, rowb = m & 15, kb = u >> 4, kk = u & 15;
            int lane2 = (rowb & 7) * 4 + ((kk & 7) >> 1);
            int reg = (rowb >> 3) + 2 * (kk >> 3);
            int half = kk & 1;
            size_t fo = ((size_t)(mb * 64 + kb)) * 512 + lane2 * 16 + reg * 2 + half;
            g_hf2[hwr + fo] = hb;
            g_hf2[hwr + fo + 8] = lb;
        }
    }
}

// ------------------ feature assembly + head MLPs ------------------
__global__ void k_feat(const float* __restrict__ head)
{
    int idx = blockIdx.x * blockDim.x + threadIdx.x;
    if (idx >= NB * FEATP) return;
    int b = idx / FEATP;
    int k = idx - b * FEATP;
    float v;
    if (k < 2)            v = head[b * 3 + 1 + k];
    else if (k < 1026)    v = g_c[b * NH + (k - 2)];
    else if (k < 2050)    v = g_hf[b * NH + (k - 1026)];
    else                  v = 0.f;
    g_feat[idx] = v;
}

__global__ __launch_bounds__(256) void k_head_gemm(
    const float* __restrict__ W3, const float* __restrict__ b3,
    const float* __restrict__ W4, const float* __restrict__ b4,
    const float* __restrict__ W5, const float* __restrict__ b5,
    const float* __restrict__ W6, const float* __restrict__ b6)
{
    const int which = blockIdx.z;
    const float* Wm = (which == 0) ? W3 : (which == 1) ? W4 : (which == 2) ? W5 : W6;
    const float* bv = (which == 0) ? b3 : (which == 1) ? b4 : (which == 2) ? b5 : b6;
    float* Cout = (which == 0) ? g_vlp : (which == 1) ? g_qlp : (which == 2) ? g_vle : g_qle;

    __shared__ float As[16][64];
    __shared__ float Bs[16][64];
    const int tid = threadIdx.x;
    const int tx = tid & 15;
    const int ty = tid >> 4;
    const int m0 = blockIdx.y * 64;
    const int n0 = blockIdx.x * 64;

    float acc[4][4];
#pragma unroll
    for (int i = 0; i < 4; ++i)
#pragma unroll
        for (int j = 0; j < 4; ++j) acc[i][j] = 0.f;

    const int KT = FEATP / 16;
    for (int kt = 0; kt < KT; ++kt) {
        const int kbase = kt * 16;
        {
            int idx = tid;
            int m  = idx >> 2;
            int k4 = (idx & 3) * 4;
            float4 v = *(const float4*)(g_feat + (size_t)(m0 + m) * FEATP + kbase + k4);
            As[k4 + 0][m] = v.x;
            As[k4 + 1][m] = v.y;
            As[k4 + 2][m] = v.z;
            As[k4 + 3][m] = v.w;
            int kb = idx >> 4;
            int nb = (idx & 15) * 4;
            int kg = kbase + kb;
            float4 w = make_float4(0.f, 0.f, 0.f, 0.f);
            if (kg < FEATR)
                w = *(const float4*)(Wm + (size_t)kg * 512 + n0 + nb);
            *(float4*)&Bs[kb][nb] = w;
        }
        __syncthreads();
#pragma unroll
        for (int kk = 0; kk < 16; ++kk) {
            float a[4], b[4];
            *(float4*)&a[0] = *(const float4*)&As[kk][ty * 4];
            *(float4*)&b[0] = *(const float4*)&Bs[kk][tx * 4];
#pragma unroll
            for (int i = 0; i < 4; ++i)
#pragma unroll
                for (int j = 0; j < 4; ++j)
                    acc[i][j] += a[i] * b[j];
        }
        __syncthreads();
    }

#pragma unroll
    for (int i = 0; i < 4; ++i) {
        int m = m0 + ty * 4 + i;
        int n = n0 + tx * 4;
        float4 r;
        r.x = acc[i][0] + bv[n + 0];
        r.y = acc[i][1] + bv[n + 1];
        r.z = acc[i][2] + bv[n + 2];
        r.w = acc[i][3] + bv[n + 3];
        r.x = r.x > 0.f ? r.x : 0.f;
        r.y = r.y > 0.f ? r.y : 0.f;
        r.z = r.z > 0.f ? r.z : 0.f;
        r.w = r.w > 0.f ? r.w : 0.f;
        *(float4*)(Cout + (size_t)m * 512 + n) = r;
    }
}

__global__ void k_combine(
    const float* __restrict__ head, const float* __restrict__ targetQ,
    const int* __restrict__ action,
    const float* __restrict__ Wsv, const float* __restrict__ bsv,
    const float* __restrict__ Wbv, const float* __restrict__ bbv,
    const float* __restrict__ Wsh, const float* __restrict__ bsh,
    const float* __restrict__ Wbh, const float* __restrict__ bbh,
    float* __restrict__ out, int out_size)
{
    const int b = blockIdx.x;
    const int tid = threadIdx.x;
    float s0 = 0.f, s1 = 0.f, s2 = 0.f, s3 = 0.f, s4 = 0.f, s5 = 0.f;
    for (int k = tid; k < 512; k += 128) {
        float vp = g_vlp[b * 512 + k];
        float qp = g_qlp[b * 512 + k];
        float ve = g_vle[b * 512 + k];
        float qe = g_qle[b * 512 + k];
        s0 += vp * Wsv[k];
        s1 += qp * Wsh[2 * k];
        s2 += qp * Wsh[2 * k + 1];
        s3 += ve * Wbv[k];
        s4 += qe * Wbh[2 * k];
        s5 += qe * Wbh[2 * k + 1];
    }
    __shared__ float red[6][128];
    red[0][tid] = s0; red[1][tid] = s1; red[2][tid] = s2;
    red[3][tid] = s3; red[4][tid] = s4; red[5][tid] = s5;
    __syncthreads();
    for (int off = 64; off > 0; off >>= 1) {
        if (tid < off) {
#pragma unroll
            for (int i = 0; i < 6; ++i) red[i][tid] += red[i][tid + off];
        }
        __syncthreads();
    }
    if (tid == 0) {
        float sellv = red[0][0] + bsv[0];
        float pa0 = red[1][0] + bsh[0];
        float pa1 = red[2][0] + bsh[1];
        float buyv = red[3][0] + bbv[0];
        float ea0 = red[4][0] + bbh[0];
        float ea1 = red[5][0] + bbh[1];
        float pm = 0.5f * (pa0 + pa1);
        float em = 0.5f * (ea0 + ea1);
        float pQ0 = pa0 - pm + sellv;
        float pQ1 = pa1 - pm + sellv;
        float eQ0 = ea0 - em + buyv;
        float eQ1 = ea1 - em + buyv;
        float isp = head[b * 3];
        float Q0, Q1;
        if (isp != 0.f) { Q0 = pQ0; Q1 = eQ1; }
        else            { Q0 = eQ0; Q1 = pQ1; }
        if (out_size >= 1 + 2 * NB) {
            out[1 + 2 * b]     = Q0;
            out[1 + 2 * b + 1] = Q1;
        }
        if (out_size >= 1 + 2 * NB + NB) {
            out[1 + 2 * NB + b] = (Q1 > Q0) ? 1.f : 0.f;
        }
        int a = action[b];
        float iv = (a == 0) ? Q0 : Q1;
        float d = targetQ[b] - iv;
        g_sq[b] = d * d;
    }
}

__global__ void k_loss(float* __restrict__ out, int out_size)
{
    __shared__ float r[256];
    int tid = threadIdx.x;
    r[tid] = g_sq[tid] + g_sq[tid + 256];
    __syncthreads();
    for (int off = 128; off > 0; off >>= 1) {
        if (tid < off) r[tid] += r[tid + off];
        __syncthreads();
    }
    if (tid == 0 && out_size >= 1) out[0] = r[0] * (1.f / 512.f);
}

// ------------------ launch ------------------
extern "C" void kernel_launch(void* const* d_in, const int* in_sizes, int n_in,
                              void* d_out, int out_size)
{
    const float* hist    = (const float*)d_in[0];
    const float* head    = (const float*)d_in[1];
    const float* targetQ = (const float*)d_in[2];
    const int*   action  = (const int*)d_in[3];
    const float* W_lstm  = (const float*)d_in[4];
    const float* b_lstm  = (const float*)d_in[5];
    const float* W3 = (const float*)d_in[6],  *b3 = (const float*)d_in[7];
    const float* W4 = (const float*)d_in[8],  *b4 = (const float*)d_in[9];
    const float* W5 = (const float*)d_in[10], *b5 = (const float*)d_in[11];
    const float* W6 = (const float*)d_in[12], *b6 = (const float*)d_in[13];
    const float* Wsv = (const float*)d_in[14], *bsv = (const float*)d_in[15];
    const float* Wbv = (const float*)d_in[16], *bbv = (const float*)d_in[17];
    const float* Wsh = (const float*)d_in[18], *bsh = (const float*)d_in[19];
    const float* Wbh = (const float*)d_in[20], *bbh = (const float*)d_in[21];
    float* out = (float*)d_out;

    k_init<<<(NB * NH * 2 + 255) / 256, 256>>>();
    k_prep_w<<<((size_t)NZ * KTOT + 255) / 256, 256>>>(W_lstm);
    k_prep_x<<<((size_t)NB * NT * NF + 255) / 256, 256>>>(hist);

    dim3 gl(64, 4);  // 256 CTAs, 2/SM, no smem, no barriers
    for (int t = 0; t < NT; ++t)
        k_step<<<gl, 256>>>(b_lstm, t);

    k_feat<<<(NB * FEATP + 255) / 256, 256>>>(head);

    dim3 gh(8, 8, 4);
    k_head_gemm<<<gh, 256>>>(W3, b3, W4, b4, W5, b5, W6, b6);

    k_combine<<<NB, 128>>>(head, targetQ, action,
                           Wsv, bsv, Wbv, bbv, Wsh, bsh, Wbh, bbh,
                           out, out_size);
    k_loss<<<1, 256>>>(out, out_size);
}